// round 15
// baseline (speedup 1.0000x reference)
#include <cuda_runtime.h>
#include <cuda_fp16.h>
#include <math.h>

#define NTOK 8192
#define CDIM 1024
#define HDIM 4096
#define NEXP 8
#define NSLOT (2*NTOK)
#define STAGES 3
#define BM 128
#define BN 128
#define BK 64
#define STAGE_U32 8192
#define STAGE_BYTES (STAGE_U32 * 4)
#define SMEM_DYN (STAGES * STAGE_BYTES)    // 98304 bytes

#define N_W1_CHUNK (NEXP * HDIM * CDIM / 4)     // 8388608 float4
#define N_X_CHUNK  (NTOK * CDIM / 4)            // 2097152
#define N_PREP     (N_W1_CHUNK + N_X_CHUNK)
#define N_W2_CHUNK (NEXP * CDIM * HDIM / 4)     // 8388608

// ---------------- device scratch ----------------
__device__ int    g_counts[NEXP];
__device__ int    g_tokens[NEXP * NTOK];
__device__ float  g_gate[NEXP * NTOK];
__device__ __half g_h[(size_t)NSLOT * HDIM];
__device__ __half g_w1h[(size_t)NEXP * HDIM * CDIM];
__device__ __half g_w2h[(size_t)NEXP * CDIM * HDIM];
__device__ __half g_xh[(size_t)NTOK * CDIM];

// ---------------- helpers ----------------
__device__ __forceinline__ float new_gelu(float v) {
    const float c = 0.7978845608028654f;
    float u = c * (v + 0.044715f * v * v * v);
    return 0.5f * v * (1.0f + tanhf(u));
}
__device__ __forceinline__ void mma_f16(float* c, const unsigned* a, const unsigned* b) {
    asm volatile(
        "mma.sync.aligned.m16n8k16.row.col.f32.f16.f16.f32 "
        "{%0,%1,%2,%3}, {%4,%5,%6,%7}, {%8,%9}, {%0,%1,%2,%3};"
        : "+f"(c[0]), "+f"(c[1]), "+f"(c[2]), "+f"(c[3])
        : "r"(a[0]), "r"(a[1]), "r"(a[2]), "r"(a[3]), "r"(b[0]), "r"(b[1]));
}
__device__ __forceinline__ void ldm_x4(unsigned* r, unsigned addr) {
    asm volatile("ldmatrix.sync.aligned.m8n8.x4.shared.b16 {%0,%1,%2,%3}, [%4];"
                 : "=r"(r[0]), "=r"(r[1]), "=r"(r[2]), "=r"(r[3]) : "r"(addr));
}
__device__ __forceinline__ void cp16(unsigned dst, const void* src, int src_size) {
    asm volatile("cp.async.cg.shared.global [%0], [%1], 16, %2;"
                 :: "r"(dst), "l"(src), "r"(src_size));
}
__device__ __forceinline__ void cp_commit() {
    asm volatile("cp.async.commit_group;" ::: "memory");
}
template <int N>
__device__ __forceinline__ void cp_wait() {
    asm volatile("cp.async.wait_group %0;" :: "n"(N) : "memory");
}
__device__ __forceinline__ void cvt_store(const float4* src, __half2* dst, size_t i) {
    float4 v = src[i];
    dst[i * 2]     = __floats2half2_rn(v.x, v.y);
    dst[i * 2 + 1] = __floats2half2_rn(v.z, v.w);
}
__device__ __forceinline__ int expert_offset(int e) {
    int off = 0;
#pragma unroll
    for (int k = 0; k < NEXP; k++) if (k < e) off += g_counts[k];
    return off;
}

// ---------------- prep: fp16-convert w1 + x ----------------
__global__ void prep_kernel(const float* __restrict__ w1,
                            const float* __restrict__ x) {
    size_t i = (size_t)blockIdx.x * 256 + threadIdx.x;
    if (i >= N_PREP) return;
    if (i < N_W1_CHUNK)
        cvt_store((const float4*)w1, (__half2*)g_w1h, i);
    else
        cvt_store((const float4*)x, (__half2*)g_xh, i - N_W1_CHUNK);
}

// ---------------- w2 conversion (zero smem) ----------------
__global__ void w2conv_kernel(const float* __restrict__ w2) {
    size_t stride = (size_t)gridDim.x * 256;
    for (size_t i = (size_t)blockIdx.x * 256 + threadIdx.x; i < N_W2_CHUNK; i += stride)
        cvt_store((const float4*)w2, (__half2*)g_w2h, i);
}

// ---------------- router (one warp per token) ----------------
__global__ void router_kernel(const float* __restrict__ x,
                              const float* __restrict__ rw) {
    int warp = (blockIdx.x * blockDim.x + threadIdx.x) >> 5;
    int lane = threadIdx.x & 31;
    if (warp >= NTOK) return;
    const float* xr = x + (size_t)warp * CDIM;

    float acc[NEXP];
#pragma unroll
    for (int e = 0; e < NEXP; e++) acc[e] = 0.f;
    for (int c = lane; c < CDIM; c += 32) {
        float xv = xr[c];
#pragma unroll
        for (int e = 0; e < NEXP; e++)
            acc[e] = fmaf(xv, rw[e * CDIM + c], acc[e]);
    }
#pragma unroll
    for (int off = 16; off > 0; off >>= 1)
#pragma unroll
        for (int e = 0; e < NEXP; e++)
            acc[e] += __shfl_xor_sync(0xffffffffu, acc[e], off);

    if (lane == 0) {
        float mx = acc[0];
#pragma unroll
        for (int e = 1; e < NEXP; e++) mx = fmaxf(mx, acc[e]);
        float p[NEXP], s = 0.f;
#pragma unroll
        for (int e = 0; e < NEXP; e++) { p[e] = expf(acc[e] - mx); s += p[e]; }
        float inv = 1.f / s;
#pragma unroll
        for (int e = 0; e < NEXP; e++) p[e] *= inv;

        int i0 = 0;
#pragma unroll
        for (int e = 1; e < NEXP; e++) if (p[e] > p[i0]) i0 = e;
        int i1 = (i0 == 0) ? 1 : 0;
#pragma unroll
        for (int e = 0; e < NEXP; e++)
            if (e != i0 && p[e] > p[i1]) i1 = e;

        float denom = p[i0] + p[i1] + 1e-8f;
        int pos0 = atomicAdd(&g_counts[i0], 1);
        g_tokens[i0 * NTOK + pos0] = warp;
        g_gate[i0 * NTOK + pos0]   = p[i0] / denom;
        int pos1 = atomicAdd(&g_counts[i1], 1);
        g_tokens[i1 * NTOK + pos1] = warp;
        g_gate[i1 * NTOK + pos1]   = p[i1] / denom;
    }
}

// =====================================================================
// FP16 mma.sync grouped GEMM (proven): BM=128 BN=128 BK=64, 256 threads,
// warp tile 64x32, m16n8k16, fp32 accum, ldmatrix fragment loads.
// =====================================================================

struct LdmCtx {
    unsigned aOff[4], bOff[2];
    unsigned aSw[4], bSw[2];
    unsigned qh, ql;
};

__device__ __forceinline__ void ldm_setup(LdmCtx& c, int lane, int wm, int wn) {
    int rr = lane & 7, q = lane >> 3;
    c.qh = q >> 1; c.ql = q & 1;
#pragma unroll
    for (int mi = 0; mi < 4; mi++) {
        int row = wm + mi * 16 + c.ql * 8 + rr;
        c.aOff[mi] = row * 128;
        c.aSw[mi]  = row & 7;
    }
#pragma unroll
    for (int p = 0; p < 2; p++) {
        int row = wn + (2 * p + c.qh) * 8 + rr;
        c.bOff[p] = row * 128;
        c.bSw[p]  = row & 7;
    }
}

__device__ __forceinline__ void compute_stage(unsigned As, unsigned Bs,
                                              const LdmCtx& c, float acc[4][4][4]) {
#pragma unroll
    for (int kk = 0; kk < 4; kk++) {
        unsigned a[4][4], b[2][4];
        const unsigned ca = kk * 2 + c.qh;
        const unsigned cb = kk * 2 + c.ql;
#pragma unroll
        for (int mi = 0; mi < 4; mi++)
            ldm_x4(a[mi], As + c.aOff[mi] + (((ca ^ c.aSw[mi])) << 4));
#pragma unroll
        for (int p = 0; p < 2; p++)
            ldm_x4(b[p], Bs + c.bOff[p] + (((cb ^ c.bSw[p])) << 4));
#pragma unroll
        for (int mi = 0; mi < 4; mi++) {
            mma_f16(acc[mi][0], a[mi], &b[0][0]);
            mma_f16(acc[mi][1], a[mi], &b[0][2]);
            mma_f16(acc[mi][2], a[mi], &b[1][0]);
            mma_f16(acc[mi][3], a[mi], &b[1][2]);
        }
    }
}

#define GEMM_PIPELINE(Kdim)                                                   \
    const int tid  = threadIdx.x;                                             \
    const int lane = tid & 31;                                                \
    const int wid  = tid >> 5;                                                \
    const int wm   = (wid & 1) * 64;                                          \
    const int wn   = (wid >> 1) * 32;                                         \
    const int g    = lane >> 2;                                               \
    const int t    = lane & 3;                                                \
    const int lc   = tid & 7;                                                 \
    const int lr   = tid >> 3;                                                \
    float acc[4][4][4];                                                       \
    _Pragma("unroll")                                                         \
    for (int mi = 0; mi < 4; mi++)                                            \
        _Pragma("unroll")                                                     \
        for (int ni = 0; ni < 4; ni++)                                        \
            _Pragma("unroll")                                                 \
            for (int r = 0; r < 4; r++) acc[mi][ni][r] = 0.f;                 \
    extern __shared__ unsigned smem[];                                        \
    const unsigned sbase = (unsigned)__cvta_generic_to_shared(smem);          \
    LdmCtx lctx; ldm_setup(lctx, lane, wm, wn);                               \
    const unsigned ldOff = lr * 128 + ((lc ^ (lr & 7)) << 4);                 \
    auto issue = [&](int stage, int kt) {                                     \
        unsigned As_s = sbase + stage * STAGE_BYTES;                          \
        unsigned Bs_s = As_s + 16384;                                         \
        _Pragma("unroll")                                                     \
        for (int j = 0; j < 4; j++) {                                         \
            unsigned off = ldOff + j * 32 * 128;                              \
            const __half* sa = aRow[j] ? aRow[j] + kt + lc * 8                \
                                       : (const __half*)bRow[0];              \
            cp16(As_s + off, sa, aRow[j] ? 16 : 0);                           \
            cp16(Bs_s + off, bRow[j] + kt + lc * 8, 16);                      \
        }                                                                     \
    };                                                                        \
    const int KT = (Kdim) / BK;                                               \
    issue(0, 0); cp_commit();                                                 \
    issue(1, BK); cp_commit();                                                \
    int cs = 0, ns = 2;                                                       \
    for (int i = 0; i < KT; i++) {                                            \
        cp_wait<STAGES - 2>();                                                \
        __syncthreads();                                                      \
        int ktn = (i + STAGES - 1) * BK;                                      \
        if (ktn < (Kdim)) issue(ns, ktn);                                     \
        cp_commit();                                                          \
        compute_stage(sbase + cs * STAGE_BYTES,                               \
                      sbase + cs * STAGE_BYTES + 16384, lctx, acc);           \
        if (++cs == STAGES) cs = 0;                                           \
        if (++ns == STAGES) ns = 0;                                           \
    }

// ---------------- GEMM1 (per-expert): g_h = fp16(gelu(x@w1^T+b1)) ---------
__global__ void __launch_bounds__(256, 2)
gemm1_kernel(const float* __restrict__ b1, int e) {
    const int cnt = g_counts[e];
    const int m0  = blockIdx.y * BM;
    if (m0 >= cnt) return;
    const int n0  = blockIdx.x * BN;
    const int off = expert_offset(e);
    const __half* w1e = g_w1h + (size_t)e * HDIM * CDIM;

    const __half* aRow[4];
    const __half* bRow[4];
    {
        const int r = threadIdx.x >> 3;
#pragma unroll
        for (int j = 0; j < 4; j++) {
            int gm = m0 + r + j * 32;
            aRow[j] = (gm < cnt) ? (g_xh + (size_t)g_tokens[e * NTOK + gm] * CDIM)
                                 : (const __half*)0;
            bRow[j] = w1e + (size_t)(n0 + r + j * 32) * CDIM;
        }
    }

    GEMM_PIPELINE(CDIM)

#pragma unroll
    for (int mi = 0; mi < 4; mi++) {
        int r0 = m0 + wm + mi * 16 + g;
#pragma unroll
        for (int ni = 0; ni < 4; ni++) {
            int col = n0 + wn + ni * 8 + t * 2;
            float bv0 = b1[e * HDIM + col];
            float bv1 = b1[e * HDIM + col + 1];
            if (r0 < cnt) {
                __half2* h = (__half2*)(g_h + (size_t)(off + r0) * HDIM + col);
                *h = __floats2half2_rn(new_gelu(acc[mi][ni][0] + bv0),
                                       new_gelu(acc[mi][ni][1] + bv1));
            }
            if (r0 + 8 < cnt) {
                __half2* h = (__half2*)(g_h + (size_t)(off + r0 + 8) * HDIM + col);
                *h = __floats2half2_rn(new_gelu(acc[mi][ni][2] + bv0),
                                       new_gelu(acc[mi][ni][3] + bv1));
            }
        }
    }
}

// ---------------- GEMM2 (per-expert): out += gate * (h@w2^T+b2) -----------
__global__ void __launch_bounds__(256, 2)
gemm2_kernel(const float* __restrict__ b2, float* __restrict__ out, int e) {
    const int cnt = g_counts[e];
    const int m0  = blockIdx.y * BM;
    if (m0 >= cnt) return;
    const int n0  = blockIdx.x * BN;
    const int off = expert_offset(e);
    const __half* w2e = g_w2h + (size_t)e * CDIM * HDIM;

    const __half* aRow[4];
    const __half* bRow[4];
    {
        const int r = threadIdx.x >> 3;
#pragma unroll
        for (int j = 0; j < 4; j++) {
            int gm = m0 + r + j * 32;
            aRow[j] = (gm < cnt) ? (g_h + (size_t)(off + gm) * HDIM) : (const __half*)0;
            bRow[j] = w2e + (size_t)(n0 + r + j * 32) * HDIM;
        }
    }

    GEMM_PIPELINE(HDIM)

#pragma unroll
    for (int mi = 0; mi < 4; mi++) {
        int r0 = m0 + wm + mi * 16 + g;
#pragma unroll
        for (int half = 0; half < 2; half++) {
            int gm = r0 + half * 8;
            if (gm >= cnt) continue;
            int token  = g_tokens[e * NTOK + gm];
            float gate = g_gate[e * NTOK + gm];
            float* orow = out + (size_t)token * CDIM;
#pragma unroll
            for (int ni = 0; ni < 4; ni++) {
                int col = n0 + wn + ni * 8 + t * 2;
                float v0 = acc[mi][ni][half * 2 + 0] + b2[e * CDIM + col];
                float v1 = acc[mi][ni][half * 2 + 1] + b2[e * CDIM + col + 1];
                atomicAdd(&orow[col], gate * v0);
                atomicAdd(&orow[col + 1], gate * v1);
            }
        }
    }
}

// ---------------- launch (2-stream expert-split pipeline) -----------------
extern "C" void kernel_launch(void* const* d_in, const int* in_sizes, int n_in,
                              void* d_out, int out_size) {
    const float* x  = (const float*)d_in[0];
    const float* rw = (const float*)d_in[1];
    const float* w1 = (const float*)d_in[2];
    const float* b1 = (const float*)d_in[3];
    const float* w2 = (const float*)d_in[4];
    const float* b2 = (const float*)d_in[5];
    float* out = (float*)d_out;

    static void* counts_addr = 0;
    static cudaStream_t s2;
    static cudaEvent_t ev0, evR, evP, evW2, evEnd;
    if (!counts_addr) {
        cudaGetSymbolAddress(&counts_addr, g_counts);
        cudaFuncSetAttribute(gemm1_kernel, cudaFuncAttributeMaxDynamicSharedMemorySize, SMEM_DYN);
        cudaFuncSetAttribute(gemm2_kernel, cudaFuncAttributeMaxDynamicSharedMemorySize, SMEM_DYN);
        cudaStreamCreateWithFlags(&s2, cudaStreamNonBlocking);
        cudaEventCreateWithFlags(&ev0,   cudaEventDisableTiming);
        cudaEventCreateWithFlags(&evR,   cudaEventDisableTiming);
        cudaEventCreateWithFlags(&evP,   cudaEventDisableTiming);
        cudaEventCreateWithFlags(&evW2,  cudaEventDisableTiming);
        cudaEventCreateWithFlags(&evEnd, cudaEventDisableTiming);
    }

    cudaMemsetAsync(out, 0, (size_t)out_size * sizeof(float), 0);
    cudaMemsetAsync(counts_addr, 0, NEXP * sizeof(int), 0);
    cudaEventRecord(ev0, 0);

    // s2: router concurrent with prep conversion
    cudaStreamWaitEvent(s2, ev0, 0);
    router_kernel<<<(NTOK * 32 + 255) / 256, 256, 0, s2>>>(x, rw);
    cudaEventRecord(evR, s2);

    // main: convert w1 + x
    prep_kernel<<<(N_PREP + 255) / 256, 256>>>(w1, x);
    cudaEventRecord(evP, 0);

    // s2: w2 conversion (after router, after prep)
    cudaStreamWaitEvent(s2, evP, 0);
    w2conv_kernel<<<2048, 256, 0, s2>>>(w2);
    cudaEventRecord(evW2, s2);

    // even experts on stream 0, odd experts on s2; per-expert g1->g2 in
    // stream order, cross-stream overlap fills wave tails.
    dim3 g1(HDIM / BN, NTOK / BM, 1);
    dim3 g2(CDIM / BN, NTOK / BM, 1);
    cudaStreamWaitEvent(0, evR, 0);     // stream0 gemm1 needs router
    cudaStreamWaitEvent(0, evW2, 0);    // and its gemm2 needs w2 (simplest: gate whole queue)
    for (int e = 0; e < NEXP; e += 2) {
        gemm1_kernel<<<g1, 256, SMEM_DYN, 0>>>(b1, e);
        gemm2_kernel<<<g2, 256, SMEM_DYN, 0>>>(b2, out, e);
    }
    for (int e = 1; e < NEXP; e += 2) { // s2 already ordered after router+prep+w2conv
        gemm1_kernel<<<g1, 256, SMEM_DYN, s2>>>(b1, e);
        gemm2_kernel<<<g2, 256, SMEM_DYN, s2>>>(b2, out, e);
    }
    cudaEventRecord(evEnd, s2);
    cudaStreamWaitEvent(0, evEnd, 0);
}

// round 16
// speedup vs baseline: 1.0474x; 1.0474x over previous
#include <cuda_runtime.h>
#include <cuda_fp16.h>
#include <math.h>

#define NTOK 8192
#define CDIM 1024
#define HDIM 4096
#define NEXP 8
#define NSLOT (2*NTOK)
#define STAGES 3
#define BM 128
#define BN 128
#define BK 64
#define STAGE_U32 8192
#define STAGE_BYTES (STAGE_U32 * 4)
#define SMEM_DYN (STAGES * STAGE_BYTES)    // 98304 bytes

#define N_W1_CHUNK (NEXP * HDIM * CDIM / 4)     // 8388608 float4
#define N_X_CHUNK  (NTOK * CDIM / 4)            // 2097152
#define N_PREP     (N_W1_CHUNK + N_X_CHUNK)
#define N_W2_CHUNK (NEXP * CDIM * HDIM / 4)     // 8388608

// ---------------- device scratch ----------------
__device__ int    g_counts[NEXP];
__device__ int    g_tokens[NEXP * NTOK];
__device__ float  g_gate[NEXP * NTOK];
__device__ __half g_h[(size_t)NSLOT * HDIM];
__device__ __half g_w1h[(size_t)NEXP * HDIM * CDIM];
__device__ __half g_w2h[(size_t)NEXP * CDIM * HDIM];
__device__ __half g_xh[(size_t)NTOK * CDIM];

// ---------------- helpers ----------------
__device__ __forceinline__ float new_gelu(float v) {
    const float c = 0.7978845608028654f;
    float u = c * (v + 0.044715f * v * v * v);
    return 0.5f * v * (1.0f + tanhf(u));
}
__device__ __forceinline__ void mma_f16(float* c, const unsigned* a, const unsigned* b) {
    asm volatile(
        "mma.sync.aligned.m16n8k16.row.col.f32.f16.f16.f32 "
        "{%0,%1,%2,%3}, {%4,%5,%6,%7}, {%8,%9}, {%0,%1,%2,%3};"
        : "+f"(c[0]), "+f"(c[1]), "+f"(c[2]), "+f"(c[3])
        : "r"(a[0]), "r"(a[1]), "r"(a[2]), "r"(a[3]), "r"(b[0]), "r"(b[1]));
}
__device__ __forceinline__ void ldm_x4(unsigned* r, unsigned addr) {
    asm volatile("ldmatrix.sync.aligned.m8n8.x4.shared.b16 {%0,%1,%2,%3}, [%4];"
                 : "=r"(r[0]), "=r"(r[1]), "=r"(r[2]), "=r"(r[3]) : "r"(addr));
}
__device__ __forceinline__ void cp16(unsigned dst, const void* src, int src_size) {
    asm volatile("cp.async.cg.shared.global [%0], [%1], 16, %2;"
                 :: "r"(dst), "l"(src), "r"(src_size));
}
__device__ __forceinline__ void cp_commit() {
    asm volatile("cp.async.commit_group;" ::: "memory");
}
template <int N>
__device__ __forceinline__ void cp_wait() {
    asm volatile("cp.async.wait_group %0;" :: "n"(N) : "memory");
}
__device__ __forceinline__ void cvt_store(const float4* src, __half2* dst, size_t i) {
    float4 v = src[i];
    dst[i * 2]     = __floats2half2_rn(v.x, v.y);
    dst[i * 2 + 1] = __floats2half2_rn(v.z, v.w);
}
__device__ __forceinline__ int expert_offset(int e) {
    int off = 0;
#pragma unroll
    for (int k = 0; k < NEXP; k++) if (k < e) off += g_counts[k];
    return off;
}

// ---------------- prep: fp16-convert w1 + x (2 float4/thread) -------------
__global__ void prep_kernel(const float* __restrict__ w1,
                            const float* __restrict__ x) {
    size_t base = (size_t)blockIdx.x * 512 + threadIdx.x;
#pragma unroll
    for (int r = 0; r < 2; r++) {
        size_t i = base + r * 256;
        if (i >= N_PREP) return;
        if (i < N_W1_CHUNK)
            cvt_store((const float4*)w1, (__half2*)g_w1h, i);
        else
            cvt_store((const float4*)x, (__half2*)g_xh, i - N_W1_CHUNK);
    }
}

// ---------------- w2 conversion (zero smem) ----------------
__global__ void w2conv_kernel(const float* __restrict__ w2) {
    size_t stride = (size_t)gridDim.x * 256;
    for (size_t i = (size_t)blockIdx.x * 256 + threadIdx.x; i < N_W2_CHUNK; i += stride)
        cvt_store((const float4*)w2, (__half2*)g_w2h, i);
}

// ---------------- router (one warp per token) ----------------
__global__ void router_kernel(const float* __restrict__ x,
                              const float* __restrict__ rw) {
    int warp = (blockIdx.x * blockDim.x + threadIdx.x) >> 5;
    int lane = threadIdx.x & 31;
    if (warp >= NTOK) return;
    const float* xr = x + (size_t)warp * CDIM;

    float acc[NEXP];
#pragma unroll
    for (int e = 0; e < NEXP; e++) acc[e] = 0.f;
    for (int c = lane; c < CDIM; c += 32) {
        float xv = xr[c];
#pragma unroll
        for (int e = 0; e < NEXP; e++)
            acc[e] = fmaf(xv, rw[e * CDIM + c], acc[e]);
    }
#pragma unroll
    for (int off = 16; off > 0; off >>= 1)
#pragma unroll
        for (int e = 0; e < NEXP; e++)
            acc[e] += __shfl_xor_sync(0xffffffffu, acc[e], off);

    if (lane == 0) {
        float mx = acc[0];
#pragma unroll
        for (int e = 1; e < NEXP; e++) mx = fmaxf(mx, acc[e]);
        float p[NEXP], s = 0.f;
#pragma unroll
        for (int e = 0; e < NEXP; e++) { p[e] = expf(acc[e] - mx); s += p[e]; }
        float inv = 1.f / s;
#pragma unroll
        for (int e = 0; e < NEXP; e++) p[e] *= inv;

        int i0 = 0;
#pragma unroll
        for (int e = 1; e < NEXP; e++) if (p[e] > p[i0]) i0 = e;
        int i1 = (i0 == 0) ? 1 : 0;
#pragma unroll
        for (int e = 0; e < NEXP; e++)
            if (e != i0 && p[e] > p[i1]) i1 = e;

        float denom = p[i0] + p[i1] + 1e-8f;
        int pos0 = atomicAdd(&g_counts[i0], 1);
        g_tokens[i0 * NTOK + pos0] = warp;
        g_gate[i0 * NTOK + pos0]   = p[i0] / denom;
        int pos1 = atomicAdd(&g_counts[i1], 1);
        g_tokens[i1 * NTOK + pos1] = warp;
        g_gate[i1 * NTOK + pos1]   = p[i1] / denom;
    }
}

// =====================================================================
// FP16 mma.sync grouped GEMM (proven): BM=128 BN=128 BK=64, 256 threads,
// warp tile 64x32, m16n8k16, fp32 accum, ldmatrix fragment loads.
// =====================================================================

struct LdmCtx {
    unsigned aOff[4], bOff[2];
    unsigned aSw[4], bSw[2];
    unsigned qh, ql;
};

__device__ __forceinline__ void ldm_setup(LdmCtx& c, int lane, int wm, int wn) {
    int rr = lane & 7, q = lane >> 3;
    c.qh = q >> 1; c.ql = q & 1;
#pragma unroll
    for (int mi = 0; mi < 4; mi++) {
        int row = wm + mi * 16 + c.ql * 8 + rr;
        c.aOff[mi] = row * 128;
        c.aSw[mi]  = row & 7;
    }
#pragma unroll
    for (int p = 0; p < 2; p++) {
        int row = wn + (2 * p + c.qh) * 8 + rr;
        c.bOff[p] = row * 128;
        c.bSw[p]  = row & 7;
    }
}

__device__ __forceinline__ void compute_stage(unsigned As, unsigned Bs,
                                              const LdmCtx& c, float acc[4][4][4]) {
#pragma unroll
    for (int kk = 0; kk < 4; kk++) {
        unsigned a[4][4], b[2][4];
        const unsigned ca = kk * 2 + c.qh;
        const unsigned cb = kk * 2 + c.ql;
#pragma unroll
        for (int mi = 0; mi < 4; mi++)
            ldm_x4(a[mi], As + c.aOff[mi] + (((ca ^ c.aSw[mi])) << 4));
#pragma unroll
        for (int p = 0; p < 2; p++)
            ldm_x4(b[p], Bs + c.bOff[p] + (((cb ^ c.bSw[p])) << 4));
#pragma unroll
        for (int mi = 0; mi < 4; mi++) {
            mma_f16(acc[mi][0], a[mi], &b[0][0]);
            mma_f16(acc[mi][1], a[mi], &b[0][2]);
            mma_f16(acc[mi][2], a[mi], &b[1][0]);
            mma_f16(acc[mi][3], a[mi], &b[1][2]);
        }
    }
}

#define GEMM_PIPELINE(Kdim)                                                   \
    const int tid  = threadIdx.x;                                             \
    const int lane = tid & 31;                                                \
    const int wid  = tid >> 5;                                                \
    const int wm   = (wid & 1) * 64;                                          \
    const int wn   = (wid >> 1) * 32;                                         \
    const int g    = lane >> 2;                                               \
    const int t    = lane & 3;                                                \
    const int lc   = tid & 7;                                                 \
    const int lr   = tid >> 3;                                                \
    float acc[4][4][4];                                                       \
    _Pragma("unroll")                                                         \
    for (int mi = 0; mi < 4; mi++)                                            \
        _Pragma("unroll")                                                     \
        for (int ni = 0; ni < 4; ni++)                                        \
            _Pragma("unroll")                                                 \
            for (int r = 0; r < 4; r++) acc[mi][ni][r] = 0.f;                 \
    extern __shared__ unsigned smem[];                                        \
    const unsigned sbase = (unsigned)__cvta_generic_to_shared(smem);          \
    LdmCtx lctx; ldm_setup(lctx, lane, wm, wn);                               \
    const unsigned ldOff = lr * 128 + ((lc ^ (lr & 7)) << 4);                 \
    auto issue = [&](int stage, int kt) {                                     \
        unsigned As_s = sbase + stage * STAGE_BYTES;                          \
        unsigned Bs_s = As_s + 16384;                                         \
        _Pragma("unroll")                                                     \
        for (int j = 0; j < 4; j++) {                                         \
            unsigned off = ldOff + j * 32 * 128;                              \
            const __half* sa = aRow[j] ? aRow[j] + kt + lc * 8                \
                                       : (const __half*)bRow[0];              \
            cp16(As_s + off, sa, aRow[j] ? 16 : 0);                           \
            cp16(Bs_s + off, bRow[j] + kt + lc * 8, 16);                      \
        }                                                                     \
    };                                                                        \
    const int KT = (Kdim) / BK;                                               \
    issue(0, 0); cp_commit();                                                 \
    issue(1, BK); cp_commit();                                                \
    int cs = 0, ns = 2;                                                       \
    for (int i = 0; i < KT; i++) {                                            \
        cp_wait<STAGES - 2>();                                                \
        __syncthreads();                                                      \
        int ktn = (i + STAGES - 1) * BK;                                      \
        if (ktn < (Kdim)) issue(ns, ktn);                                     \
        cp_commit();                                                          \
        compute_stage(sbase + cs * STAGE_BYTES,                               \
                      sbase + cs * STAGE_BYTES + 16384, lctx, acc);           \
        if (++cs == STAGES) cs = 0;                                           \
        if (++ns == STAGES) ns = 0;                                           \
    }

// ---------------- GEMM1 (expert-half): z = expert - ebase -----------------
__global__ void __launch_bounds__(256, 2)
gemm1_kernel(const float* __restrict__ b1, int ebase) {
    const int e   = ebase + blockIdx.z;
    const int cnt = g_counts[e];
    const int m0  = blockIdx.y * BM;
    if (m0 >= cnt) return;
    const int n0  = blockIdx.x * BN;
    const int off = expert_offset(e);
    const __half* w1e = g_w1h + (size_t)e * HDIM * CDIM;

    const __half* aRow[4];
    const __half* bRow[4];
    {
        const int r = threadIdx.x >> 3;
#pragma unroll
        for (int j = 0; j < 4; j++) {
            int gm = m0 + r + j * 32;
            aRow[j] = (gm < cnt) ? (g_xh + (size_t)g_tokens[e * NTOK + gm] * CDIM)
                                 : (const __half*)0;
            bRow[j] = w1e + (size_t)(n0 + r + j * 32) * CDIM;
        }
    }

    GEMM_PIPELINE(CDIM)

#pragma unroll
    for (int mi = 0; mi < 4; mi++) {
        int r0 = m0 + wm + mi * 16 + g;
#pragma unroll
        for (int ni = 0; ni < 4; ni++) {
            int col = n0 + wn + ni * 8 + t * 2;
            float bv0 = b1[e * HDIM + col];
            float bv1 = b1[e * HDIM + col + 1];
            if (r0 < cnt) {
                __half2* h = (__half2*)(g_h + (size_t)(off + r0) * HDIM + col);
                *h = __floats2half2_rn(new_gelu(acc[mi][ni][0] + bv0),
                                       new_gelu(acc[mi][ni][1] + bv1));
            }
            if (r0 + 8 < cnt) {
                __half2* h = (__half2*)(g_h + (size_t)(off + r0 + 8) * HDIM + col);
                *h = __floats2half2_rn(new_gelu(acc[mi][ni][2] + bv0),
                                       new_gelu(acc[mi][ni][3] + bv1));
            }
        }
    }
}

// ---------------- GEMM2 (expert-half): out += gate*(h@w2^T+b2) ------------
__global__ void __launch_bounds__(256, 2)
gemm2_kernel(const float* __restrict__ b2, float* __restrict__ out, int ebase) {
    const int e   = ebase + blockIdx.z;
    const int cnt = g_counts[e];
    const int m0  = blockIdx.y * BM;
    if (m0 >= cnt) return;
    const int n0  = blockIdx.x * BN;
    const int off = expert_offset(e);
    const __half* w2e = g_w2h + (size_t)e * CDIM * HDIM;

    const __half* aRow[4];
    const __half* bRow[4];
    {
        const int r = threadIdx.x >> 3;
#pragma unroll
        for (int j = 0; j < 4; j++) {
            int gm = m0 + r + j * 32;
            aRow[j] = (gm < cnt) ? (g_h + (size_t)(off + gm) * HDIM) : (const __half*)0;
            bRow[j] = w2e + (size_t)(n0 + r + j * 32) * HDIM;
        }
    }

    GEMM_PIPELINE(HDIM)

#pragma unroll
    for (int mi = 0; mi < 4; mi++) {
        int r0 = m0 + wm + mi * 16 + g;
#pragma unroll
        for (int half = 0; half < 2; half++) {
            int gm = r0 + half * 8;
            if (gm >= cnt) continue;
            int token  = g_tokens[e * NTOK + gm];
            float gate = g_gate[e * NTOK + gm];
            float* orow = out + (size_t)token * CDIM;
#pragma unroll
            for (int ni = 0; ni < 4; ni++) {
                int col = n0 + wn + ni * 8 + t * 2;
                float v0 = acc[mi][ni][half * 2 + 0] + b2[e * CDIM + col];
                float v1 = acc[mi][ni][half * 2 + 1] + b2[e * CDIM + col + 1];
                atomicAdd(&orow[col], gate * v0);
                atomicAdd(&orow[col + 1], gate * v1);
            }
        }
    }
}

// ---------------- launch (2-stream half-split pipeline) -------------------
extern "C" void kernel_launch(void* const* d_in, const int* in_sizes, int n_in,
                              void* d_out, int out_size) {
    const float* x  = (const float*)d_in[0];
    const float* rw = (const float*)d_in[1];
    const float* w1 = (const float*)d_in[2];
    const float* b1 = (const float*)d_in[3];
    const float* w2 = (const float*)d_in[4];
    const float* b2 = (const float*)d_in[5];
    float* out = (float*)d_out;

    static void* counts_addr = 0;
    static cudaStream_t s2;
    static cudaEvent_t ev0, evR, evP, evW2, evEnd;
    if (!counts_addr) {
        cudaGetSymbolAddress(&counts_addr, g_counts);
        cudaFuncSetAttribute(gemm1_kernel, cudaFuncAttributeMaxDynamicSharedMemorySize, SMEM_DYN);
        cudaFuncSetAttribute(gemm2_kernel, cudaFuncAttributeMaxDynamicSharedMemorySize, SMEM_DYN);
        cudaStreamCreateWithFlags(&s2, cudaStreamNonBlocking);
        cudaEventCreateWithFlags(&ev0,   cudaEventDisableTiming);
        cudaEventCreateWithFlags(&evR,   cudaEventDisableTiming);
        cudaEventCreateWithFlags(&evP,   cudaEventDisableTiming);
        cudaEventCreateWithFlags(&evW2,  cudaEventDisableTiming);
        cudaEventCreateWithFlags(&evEnd, cudaEventDisableTiming);
    }

    cudaMemsetAsync(out, 0, (size_t)out_size * sizeof(float), 0);
    cudaMemsetAsync(counts_addr, 0, NEXP * sizeof(int), 0);
    cudaEventRecord(ev0, 0);

    // s2: router concurrent with prep conversion
    cudaStreamWaitEvent(s2, ev0, 0);
    router_kernel<<<(NTOK * 32 + 255) / 256, 256, 0, s2>>>(x, rw);
    cudaEventRecord(evR, s2);

    // main: convert w1 + x
    prep_kernel<<<(N_PREP + 511) / 512, 256>>>(w1, x);
    cudaEventRecord(evP, 0);

    // s2: w2 conversion (after router; after prep via evP)
    cudaStreamWaitEvent(s2, evP, 0);
    w2conv_kernel<<<2048, 256, 0, s2>>>(w2);
    cudaEventRecord(evW2, s2);

    dim3 g1(HDIM / BN, NTOK / BM, NEXP / 2);
    dim3 g2(CDIM / BN, NTOK / BM, NEXP / 2);

    // stream 0: experts 0-3 (g1 needs router via evR; g2 needs w2 via evW2)
    cudaStreamWaitEvent(0, evR, 0);
    gemm1_kernel<<<g1, 256, SMEM_DYN, 0>>>(b1, 0);
    cudaStreamWaitEvent(0, evW2, 0);
    gemm2_kernel<<<g2, 256, SMEM_DYN, 0>>>(b2, out, 0);

    // s2: experts 4-7 (g1 after router+prep+w2conv by stream order)
    gemm1_kernel<<<g1, 256, SMEM_DYN, s2>>>(b1, 4);
    gemm2_kernel<<<g2, 256, SMEM_DYN, s2>>>(b2, out, 4);
    cudaEventRecord(evEnd, s2);
    cudaStreamWaitEvent(0, evEnd, 0);
}

// round 17
// speedup vs baseline: 1.0937x; 1.0442x over previous
#include <cuda_runtime.h>
#include <cuda_fp16.h>
#include <math.h>

#define NTOK 8192
#define CDIM 1024
#define HDIM 4096
#define NEXP 8
#define NSLOT (2*NTOK)
#define STAGES 3
#define BM 128
#define BN 128
#define BK 64
#define STAGE_U32 8192
#define STAGE_BYTES (STAGE_U32 * 4)
#define SMEM_DYN (STAGES * STAGE_BYTES)    // 98304 bytes

#define N_W1_CHUNK (NEXP * HDIM * CDIM / 4)     // 8388608 float4
#define N_X_CHUNK  (NTOK * CDIM / 4)            // 2097152
#define N_PREP     (N_W1_CHUNK + N_X_CHUNK)
#define N_W2_CHUNK (NEXP * CDIM * HDIM / 4)     // 8388608

// ---------------- device scratch ----------------
__device__ int    g_counts[NEXP];
__device__ int    g_tokens[NEXP * NTOK];
__device__ float  g_gate[NEXP * NTOK];
__device__ __half g_h[(size_t)NSLOT * HDIM];
__device__ __half g_w1h[(size_t)NEXP * HDIM * CDIM];
__device__ __half g_w2h[(size_t)NEXP * CDIM * HDIM];
__device__ __half g_xh[(size_t)NTOK * CDIM];

// ---------------- helpers ----------------
__device__ __forceinline__ float new_gelu(float v) {
    const float c = 0.7978845608028654f;
    float u = c * (v + 0.044715f * v * v * v);
    return 0.5f * v * (1.0f + tanhf(u));
}
__device__ __forceinline__ void mma_f16(float* c, const unsigned* a, const unsigned* b) {
    asm volatile(
        "mma.sync.aligned.m16n8k16.row.col.f32.f16.f16.f32 "
        "{%0,%1,%2,%3}, {%4,%5,%6,%7}, {%8,%9}, {%0,%1,%2,%3};"
        : "+f"(c[0]), "+f"(c[1]), "+f"(c[2]), "+f"(c[3])
        : "r"(a[0]), "r"(a[1]), "r"(a[2]), "r"(a[3]), "r"(b[0]), "r"(b[1]));
}
__device__ __forceinline__ void ldm_x4(unsigned* r, unsigned addr) {
    asm volatile("ldmatrix.sync.aligned.m8n8.x4.shared.b16 {%0,%1,%2,%3}, [%4];"
                 : "=r"(r[0]), "=r"(r[1]), "=r"(r[2]), "=r"(r[3]) : "r"(addr));
}
__device__ __forceinline__ void cp16(unsigned dst, const void* src, int src_size) {
    asm volatile("cp.async.cg.shared.global [%0], [%1], 16, %2;"
                 :: "r"(dst), "l"(src), "r"(src_size));
}
__device__ __forceinline__ void cp_commit() {
    asm volatile("cp.async.commit_group;" ::: "memory");
}
template <int N>
__device__ __forceinline__ void cp_wait() {
    asm volatile("cp.async.wait_group %0;" :: "n"(N) : "memory");
}
__device__ __forceinline__ void cvt_store(const float4* src, __half2* dst, size_t i) {
    float4 v = src[i];
    dst[i * 2]     = __floats2half2_rn(v.x, v.y);
    dst[i * 2 + 1] = __floats2half2_rn(v.z, v.w);
}
__device__ __forceinline__ int expert_offset(int e) {
    int off = 0;
#pragma unroll
    for (int k = 0; k < NEXP; k++) if (k < e) off += g_counts[k];
    return off;
}

// ---------------- prep: fp16-convert w1 + x (2 float4/thread) -------------
__global__ void prep_kernel(const float* __restrict__ w1,
                            const float* __restrict__ x) {
    size_t base = (size_t)blockIdx.x * 512 + threadIdx.x;
#pragma unroll
    for (int r = 0; r < 2; r++) {
        size_t i = base + r * 256;
        if (i >= N_PREP) return;
        if (i < N_W1_CHUNK)
            cvt_store((const float4*)w1, (__half2*)g_w1h, i);
        else
            cvt_store((const float4*)x, (__half2*)g_xh, i - N_W1_CHUNK);
    }
}

// ---------------- w2 conversion (zero smem, co-resides with GEMM1) -------
__global__ void w2conv_kernel(const float* __restrict__ w2) {
    size_t stride = (size_t)gridDim.x * 256;
    for (size_t i = (size_t)blockIdx.x * 256 + threadIdx.x; i < N_W2_CHUNK; i += stride)
        cvt_store((const float4*)w2, (__half2*)g_w2h, i);
}

// ---------------- router (one warp per token) ----------------
__global__ void router_kernel(const float* __restrict__ x,
                              const float* __restrict__ rw) {
    int warp = (blockIdx.x * blockDim.x + threadIdx.x) >> 5;
    int lane = threadIdx.x & 31;
    if (warp >= NTOK) return;
    const float* xr = x + (size_t)warp * CDIM;

    float acc[NEXP];
#pragma unroll
    for (int e = 0; e < NEXP; e++) acc[e] = 0.f;
    for (int c = lane; c < CDIM; c += 32) {
        float xv = xr[c];
#pragma unroll
        for (int e = 0; e < NEXP; e++)
            acc[e] = fmaf(xv, rw[e * CDIM + c], acc[e]);
    }
#pragma unroll
    for (int off = 16; off > 0; off >>= 1)
#pragma unroll
        for (int e = 0; e < NEXP; e++)
            acc[e] += __shfl_xor_sync(0xffffffffu, acc[e], off);

    if (lane == 0) {
        float mx = acc[0];
#pragma unroll
        for (int e = 1; e < NEXP; e++) mx = fmaxf(mx, acc[e]);
        float p[NEXP], s = 0.f;
#pragma unroll
        for (int e = 0; e < NEXP; e++) { p[e] = expf(acc[e] - mx); s += p[e]; }
        float inv = 1.f / s;
#pragma unroll
        for (int e = 0; e < NEXP; e++) p[e] *= inv;

        int i0 = 0;
#pragma unroll
        for (int e = 1; e < NEXP; e++) if (p[e] > p[i0]) i0 = e;
        int i1 = (i0 == 0) ? 1 : 0;
#pragma unroll
        for (int e = 0; e < NEXP; e++)
            if (e != i0 && p[e] > p[i1]) i1 = e;

        float denom = p[i0] + p[i1] + 1e-8f;
        int pos0 = atomicAdd(&g_counts[i0], 1);
        g_tokens[i0 * NTOK + pos0] = warp;
        g_gate[i0 * NTOK + pos0]   = p[i0] / denom;
        int pos1 = atomicAdd(&g_counts[i1], 1);
        g_tokens[i1 * NTOK + pos1] = warp;
        g_gate[i1 * NTOK + pos1]   = p[i1] / denom;
    }
}

// =====================================================================
// FP16 mma.sync grouped GEMM (proven): BM=128 BN=128 BK=64, 256 threads,
// warp tile 64x32, m16n8k16, fp32 accum, ldmatrix fragment loads.
// =====================================================================

struct LdmCtx {
    unsigned aOff[4], bOff[2];
    unsigned aSw[4], bSw[2];
    unsigned qh, ql;
};

__device__ __forceinline__ void ldm_setup(LdmCtx& c, int lane, int wm, int wn) {
    int rr = lane & 7, q = lane >> 3;
    c.qh = q >> 1; c.ql = q & 1;
#pragma unroll
    for (int mi = 0; mi < 4; mi++) {
        int row = wm + mi * 16 + c.ql * 8 + rr;
        c.aOff[mi] = row * 128;
        c.aSw[mi]  = row & 7;
    }
#pragma unroll
    for (int p = 0; p < 2; p++) {
        int row = wn + (2 * p + c.qh) * 8 + rr;
        c.bOff[p] = row * 128;
        c.bSw[p]  = row & 7;
    }
}

__device__ __forceinline__ void compute_stage(unsigned As, unsigned Bs,
                                              const LdmCtx& c, float acc[4][4][4]) {
#pragma unroll
    for (int kk = 0; kk < 4; kk++) {
        unsigned a[4][4], b[2][4];
        const unsigned ca = kk * 2 + c.qh;
        const unsigned cb = kk * 2 + c.ql;
#pragma unroll
        for (int mi = 0; mi < 4; mi++)
            ldm_x4(a[mi], As + c.aOff[mi] + (((ca ^ c.aSw[mi])) << 4));
#pragma unroll
        for (int p = 0; p < 2; p++)
            ldm_x4(b[p], Bs + c.bOff[p] + (((cb ^ c.bSw[p])) << 4));
#pragma unroll
        for (int mi = 0; mi < 4; mi++) {
            mma_f16(acc[mi][0], a[mi], &b[0][0]);
            mma_f16(acc[mi][1], a[mi], &b[0][2]);
            mma_f16(acc[mi][2], a[mi], &b[1][0]);
            mma_f16(acc[mi][3], a[mi], &b[1][2]);
        }
    }
}

#define GEMM_PIPELINE(Kdim)                                                   \
    const int tid  = threadIdx.x;                                             \
    const int lane = tid & 31;                                                \
    const int wid  = tid >> 5;                                                \
    const int wm   = (wid & 1) * 64;                                          \
    const int wn   = (wid >> 1) * 32;                                         \
    const int g    = lane >> 2;                                               \
    const int t    = lane & 3;                                                \
    const int lc   = tid & 7;                                                 \
    const int lr   = tid >> 3;                                                \
    float acc[4][4][4];                                                       \
    _Pragma("unroll")                                                         \
    for (int mi = 0; mi < 4; mi++)                                            \
        _Pragma("unroll")                                                     \
        for (int ni = 0; ni < 4; ni++)                                        \
            _Pragma("unroll")                                                 \
            for (int r = 0; r < 4; r++) acc[mi][ni][r] = 0.f;                 \
    extern __shared__ unsigned smem[];                                        \
    const unsigned sbase = (unsigned)__cvta_generic_to_shared(smem);          \
    LdmCtx lctx; ldm_setup(lctx, lane, wm, wn);                               \
    const unsigned ldOff = lr * 128 + ((lc ^ (lr & 7)) << 4);                 \
    auto issue = [&](int stage, int kt) {                                     \
        unsigned As_s = sbase + stage * STAGE_BYTES;                          \
        unsigned Bs_s = As_s + 16384;                                         \
        _Pragma("unroll")                                                     \
        for (int j = 0; j < 4; j++) {                                         \
            unsigned off = ldOff + j * 32 * 128;                              \
            const __half* sa = aRow[j] ? aRow[j] + kt + lc * 8                \
                                       : (const __half*)bRow[0];              \
            cp16(As_s + off, sa, aRow[j] ? 16 : 0);                           \
            cp16(Bs_s + off, bRow[j] + kt + lc * 8, 16);                      \
        }                                                                     \
    };                                                                        \
    const int KT = (Kdim) / BK;                                               \
    issue(0, 0); cp_commit();                                                 \
    issue(1, BK); cp_commit();                                                \
    int cs = 0, ns = 2;                                                       \
    for (int i = 0; i < KT; i++) {                                            \
        cp_wait<STAGES - 2>();                                                \
        __syncthreads();                                                      \
        int ktn = (i + STAGES - 1) * BK;                                      \
        if (ktn < (Kdim)) issue(ns, ktn);                                     \
        cp_commit();                                                          \
        compute_stage(sbase + cs * STAGE_BYTES,                               \
                      sbase + cs * STAGE_BYTES + 16384, lctx, acc);           \
        if (++cs == STAGES) cs = 0;                                           \
        if (++ns == STAGES) ns = 0;                                           \
    }

// ---------------- GEMM1: g_h = fp16(gelu(xh[tok] @ w1h^T + b1)) -----------
__global__ void __launch_bounds__(256, 2)
gemm1_kernel(const float* __restrict__ b1) {
    const int e   = blockIdx.z;
    const int cnt = g_counts[e];
    const int m0  = blockIdx.y * BM;
    if (m0 >= cnt) return;
    const int n0  = blockIdx.x * BN;
    const int off = expert_offset(e);
    const __half* w1e = g_w1h + (size_t)e * HDIM * CDIM;

    const __half* aRow[4];
    const __half* bRow[4];
    {
        const int r = threadIdx.x >> 3;
#pragma unroll
        for (int j = 0; j < 4; j++) {
            int gm = m0 + r + j * 32;
            aRow[j] = (gm < cnt) ? (g_xh + (size_t)g_tokens[e * NTOK + gm] * CDIM)
                                 : (const __half*)0;
            bRow[j] = w1e + (size_t)(n0 + r + j * 32) * CDIM;
        }
    }

    GEMM_PIPELINE(CDIM)

#pragma unroll
    for (int mi = 0; mi < 4; mi++) {
        int r0 = m0 + wm + mi * 16 + g;
#pragma unroll
        for (int ni = 0; ni < 4; ni++) {
            int col = n0 + wn + ni * 8 + t * 2;
            float bv0 = b1[e * HDIM + col];
            float bv1 = b1[e * HDIM + col + 1];
            if (r0 < cnt) {
                __half2* h = (__half2*)(g_h + (size_t)(off + r0) * HDIM + col);
                *h = __floats2half2_rn(new_gelu(acc[mi][ni][0] + bv0),
                                       new_gelu(acc[mi][ni][1] + bv1));
            }
            if (r0 + 8 < cnt) {
                __half2* h = (__half2*)(g_h + (size_t)(off + r0 + 8) * HDIM + col);
                *h = __floats2half2_rn(new_gelu(acc[mi][ni][2] + bv0),
                                       new_gelu(acc[mi][ni][3] + bv1));
            }
        }
    }
}

// ---------------- GEMM2: out += gate * (h @ w2h^T + b2) -------------------
__global__ void __launch_bounds__(256, 2)
gemm2_kernel(const float* __restrict__ b2, float* __restrict__ out) {
    const int e   = blockIdx.z;
    const int cnt = g_counts[e];
    const int m0  = blockIdx.y * BM;
    if (m0 >= cnt) return;
    const int n0  = blockIdx.x * BN;
    const int off = expert_offset(e);
    const __half* w2e = g_w2h + (size_t)e * CDIM * HDIM;

    const __half* aRow[4];
    const __half* bRow[4];
    {
        const int r = threadIdx.x >> 3;
#pragma unroll
        for (int j = 0; j < 4; j++) {
            int gm = m0 + r + j * 32;
            aRow[j] = (gm < cnt) ? (g_h + (size_t)(off + gm) * HDIM) : (const __half*)0;
            bRow[j] = w2e + (size_t)(n0 + r + j * 32) * HDIM;
        }
    }

    GEMM_PIPELINE(HDIM)

#pragma unroll
    for (int mi = 0; mi < 4; mi++) {
        int r0 = m0 + wm + mi * 16 + g;
#pragma unroll
        for (int half = 0; half < 2; half++) {
            int gm = r0 + half * 8;
            if (gm >= cnt) continue;
            int token  = g_tokens[e * NTOK + gm];
            float gate = g_gate[e * NTOK + gm];
            float* orow = out + (size_t)token * CDIM;
#pragma unroll
            for (int ni = 0; ni < 4; ni++) {
                int col = n0 + wn + ni * 8 + t * 2;
                float v0 = acc[mi][ni][half * 2 + 0] + b2[e * CDIM + col];
                float v1 = acc[mi][ni][half * 2 + 1] + b2[e * CDIM + col + 1];
                atomicAdd(&orow[col], gate * v0);
                atomicAdd(&orow[col + 1], gate * v1);
            }
        }
    }
}

// ---------------- launch (round-13 structure + serial-path trims) ---------
extern "C" void kernel_launch(void* const* d_in, const int* in_sizes, int n_in,
                              void* d_out, int out_size) {
    const float* x  = (const float*)d_in[0];
    const float* rw = (const float*)d_in[1];
    const float* w1 = (const float*)d_in[2];
    const float* b1 = (const float*)d_in[3];
    const float* w2 = (const float*)d_in[4];
    const float* b2 = (const float*)d_in[5];
    float* out = (float*)d_out;

    static void* counts_addr = 0;
    static cudaStream_t s2;
    static cudaEvent_t ev0, evR, evP, evW2;
    if (!counts_addr) {
        cudaGetSymbolAddress(&counts_addr, g_counts);
        cudaFuncSetAttribute(gemm1_kernel, cudaFuncAttributeMaxDynamicSharedMemorySize, SMEM_DYN);
        cudaFuncSetAttribute(gemm2_kernel, cudaFuncAttributeMaxDynamicSharedMemorySize, SMEM_DYN);
        cudaStreamCreateWithFlags(&s2, cudaStreamNonBlocking);
        cudaEventCreateWithFlags(&ev0,  cudaEventDisableTiming);
        cudaEventCreateWithFlags(&evR,  cudaEventDisableTiming);
        cudaEventCreateWithFlags(&evP,  cudaEventDisableTiming);
        cudaEventCreateWithFlags(&evW2, cudaEventDisableTiming);
    }

    cudaMemsetAsync(counts_addr, 0, NEXP * sizeof(int), 0);
    cudaEventRecord(ev0, 0);

    // s2: router concurrent with prep; out-zeroing hidden here too
    cudaStreamWaitEvent(s2, ev0, 0);
    router_kernel<<<(NTOK * 32 + 255) / 256, 256, 0, s2>>>(x, rw);
    cudaEventRecord(evR, s2);
    cudaMemsetAsync(out, 0, (size_t)out_size * sizeof(float), s2);

    // main: convert w1 + x
    prep_kernel<<<(N_PREP + 511) / 512, 256>>>(w1, x);
    cudaEventRecord(evP, 0);

    // s2: w2 conversion concurrent with GEMM1 (zero-smem)
    cudaStreamWaitEvent(s2, evP, 0);
    w2conv_kernel<<<4096, 256, 0, s2>>>(w2);
    cudaEventRecord(evW2, s2);

    // main: GEMM1 after prep (stream order) + router (event)
    cudaStreamWaitEvent(0, evR, 0);
    dim3 g1(HDIM / BN, NTOK / BM, NEXP);
    gemm1_kernel<<<g1, 256, SMEM_DYN>>>(b1);

    // main: GEMM2 after GEMM1 (stream order) + w2/memset(out) (event covers both)
    cudaStreamWaitEvent(0, evW2, 0);
    dim3 g2(CDIM / BN, NTOK / BM, NEXP);
    gemm2_kernel<<<g2, 256, SMEM_DYN>>>(b2, out);
}